// round 13
// baseline (speedup 1.0000x reference)
#include <cuda_runtime.h>
#include <cuda_bf16.h>
#include <cstddef>

#define NSEED 1024
#define NPTS  8192
#define NSAMP 64
#define NDEPTH 4

typedef unsigned long long ull;

__device__ float g_feat[2 * NSEED * NDEPTH * NSAMP * 3];   // ~6.3 MB
__device__ float g_vp[2 * NSEED * NDEPTH * 256];           // ~8.4 MB
// pre-split bf16 weights (hi || lo along k), padded rows for ldmatrix
__device__ __align__(16) __nv_bfloat16 g_w2p[128 * 136];   // row 272B
__device__ __align__(16) __nv_bfloat16 g_w3p[256 * 264];   // row 528B

// ---------------- helpers ---------------------------------------------------
__device__ __forceinline__ void fma2(ull& d, ull a, ull b) {
    asm("fma.rn.f32x2 %0, %1, %2, %0;" : "+l"(d) : "l"(a), "l"(b));
}
__device__ __forceinline__ float hsum2(ull v) {
    float lo, hi; asm("mov.b64 {%0, %1}, %2;" : "=f"(lo), "=f"(hi) : "l"(v));
    return lo + hi;
}
__device__ __forceinline__ void cpasync16(void* sdst, const void* gsrc) {
    unsigned s = (unsigned)__cvta_generic_to_shared(sdst);
    asm volatile("cp.async.ca.shared.global [%0], [%1], 16;" :: "r"(s), "l"(gsrc));
}
__device__ __forceinline__ void cpcommit() { asm volatile("cp.async.commit_group;"); }

__device__ __forceinline__ void ldsm4(unsigned a, unsigned& r0, unsigned& r1,
                                      unsigned& r2, unsigned& r3) {
    asm volatile("ldmatrix.sync.aligned.m8n8.x4.shared.b16 {%0,%1,%2,%3}, [%4];"
                 : "=r"(r0), "=r"(r1), "=r"(r2), "=r"(r3) : "r"(a));
}
__device__ __forceinline__ void mma_bf16(float* c, const unsigned* a, unsigned b0, unsigned b1) {
    asm volatile("mma.sync.aligned.m16n8k16.row.col.f32.bf16.bf16.f32 "
                 "{%0,%1,%2,%3}, {%4,%5,%6,%7}, {%8,%9}, {%0,%1,%2,%3};"
                 : "+f"(c[0]), "+f"(c[1]), "+f"(c[2]), "+f"(c[3])
                 : "r"(a[0]), "r"(a[1]), "r"(a[2]), "r"(a[3]), "r"(b0), "r"(b1));
}

// Warp GEMM M32 x N64, K = NI*16, 3-term split.
template<int NI, int AS, int BS, int LO>
__device__ __forceinline__ void mma_block_n64(unsigned aB, unsigned bB, float (&acc)[2][8][4]) {
    int lane = threadIdx.x & 31;
    unsigned ar = aB + (lane & 15) * AS + (lane >> 4) * 16;
    unsigned br = bB + (lane & 15) * BS + (lane >> 4) * 16;
    #pragma unroll 1
    for (int i = 0; i < NI; ++i) {
        unsigned ah[2][4], al[2][4], bh[4][4], bl[4][4];
        ldsm4(ar + 32 * i,           ah[0][0], ah[0][1], ah[0][2], ah[0][3]);
        ldsm4(ar + 16 * AS + 32 * i, ah[1][0], ah[1][1], ah[1][2], ah[1][3]);
        #pragma unroll
        for (int g = 0; g < 4; ++g)
            ldsm4(br + g * (16 * BS) + 32 * i, bh[g][0], bh[g][1], bh[g][2], bh[g][3]);
        #pragma unroll
        for (int m = 0; m < 2; ++m)
            #pragma unroll
            for (int g = 0; g < 4; ++g) {
                mma_bf16(acc[m][2 * g + 0], ah[m], bh[g][0], bh[g][2]);
                mma_bf16(acc[m][2 * g + 1], ah[m], bh[g][1], bh[g][3]);
            }
        #pragma unroll
        for (int g = 0; g < 4; ++g)
            ldsm4(br + g * (16 * BS) + LO + 32 * i, bl[g][0], bl[g][1], bl[g][2], bl[g][3]);
        #pragma unroll
        for (int m = 0; m < 2; ++m)
            #pragma unroll
            for (int g = 0; g < 4; ++g) {
                mma_bf16(acc[m][2 * g + 0], ah[m], bl[g][0], bl[g][2]);
                mma_bf16(acc[m][2 * g + 1], ah[m], bl[g][1], bl[g][3]);
            }
        ldsm4(ar + LO + 32 * i,           al[0][0], al[0][1], al[0][2], al[0][3]);
        ldsm4(ar + 16 * AS + LO + 32 * i, al[1][0], al[1][1], al[1][2], al[1][3]);
        #pragma unroll
        for (int m = 0; m < 2; ++m)
            #pragma unroll
            for (int g = 0; g < 4; ++g) {
                mma_bf16(acc[m][2 * g + 0], al[m], bh[g][0], bh[g][2]);
                mma_bf16(acc[m][2 * g + 1], al[m], bh[g][1], bh[g][3]);
            }
    }
}

// Warp GEMM M32 x (2 x N16) over TWO quarter buffers sharing A-fragments:
// 8 ldsm feed 24 MMAs.
template<int NI, int AS, int BS, int LO>
__device__ __forceinline__ void mma_block_n16_pair(unsigned aB, unsigned b0B, unsigned b1B,
                                                   float (&acc)[2][2][2][4]) {
    int lane = threadIdx.x & 31;
    unsigned ar = aB + (lane & 15) * AS + (lane >> 4) * 16;
    unsigned br0 = b0B + (lane & 15) * BS + (lane >> 4) * 16;
    unsigned br1 = b1B + (lane & 15) * BS + (lane >> 4) * 16;
    #pragma unroll 1
    for (int i = 0; i < NI; ++i) {
        unsigned ah[2][4], al[2][4], bh[2][4], bl[2][4];
        ldsm4(ar + 32 * i,                ah[0][0], ah[0][1], ah[0][2], ah[0][3]);
        ldsm4(ar + 16 * AS + 32 * i,      ah[1][0], ah[1][1], ah[1][2], ah[1][3]);
        ldsm4(ar + LO + 32 * i,           al[0][0], al[0][1], al[0][2], al[0][3]);
        ldsm4(ar + 16 * AS + LO + 32 * i, al[1][0], al[1][1], al[1][2], al[1][3]);
        ldsm4(br0 + 32 * i,      bh[0][0], bh[0][1], bh[0][2], bh[0][3]);
        ldsm4(br0 + LO + 32 * i, bl[0][0], bl[0][1], bl[0][2], bl[0][3]);
        ldsm4(br1 + 32 * i,      bh[1][0], bh[1][1], bh[1][2], bh[1][3]);
        ldsm4(br1 + LO + 32 * i, bl[1][0], bl[1][1], bl[1][2], bl[1][3]);
        #pragma unroll
        for (int b = 0; b < 2; ++b)
            #pragma unroll
            for (int m = 0; m < 2; ++m) {
                mma_bf16(acc[b][m][0], ah[m], bh[b][0], bh[b][2]);
                mma_bf16(acc[b][m][1], ah[m], bh[b][1], bh[b][3]);
                mma_bf16(acc[b][m][0], ah[m], bl[b][0], bl[b][2]);
                mma_bf16(acc[b][m][1], ah[m], bl[b][1], bl[b][3]);
                mma_bf16(acc[b][m][0], al[m], bh[b][0], bh[b][2]);
                mma_bf16(acc[b][m][1], al[m], bh[b][1], bh[b][3]);
            }
    }
}

// ---------------------------------------------------------------------------
// Prep: split W2/W3 into bf16 hi/lo padded rows.
// ---------------------------------------------------------------------------
__global__ void prep_w2(const float* __restrict__ cw2) {
    int idx = blockIdx.x * 256 + threadIdx.x;   // 128 x 64
    if (idx >= 128 * 64) return;
    int j = idx >> 6, k = idx & 63;
    float w = cw2[idx];
    __nv_bfloat16 hi = __float2bfloat16(w);
    __nv_bfloat16 lo = __float2bfloat16(w - __bfloat162float(hi));
    g_w2p[j * 136 + k] = hi;
    g_w2p[j * 136 + 64 + k] = lo;
}
__global__ void prep_w3(const float* __restrict__ cw3) {
    int idx = blockIdx.x * 256 + threadIdx.x;   // 256 x 128
    if (idx >= 256 * 128) return;
    int j = idx >> 7, k = idx & 127;
    float w = cw3[idx];
    __nv_bfloat16 hi = __float2bfloat16(w);
    __nv_bfloat16 lo = __float2bfloat16(w - __bfloat162float(hi));
    g_w3p[j * 264 + k] = hi;
    g_w3p[j * 264 + 128 + k] = lo;
}

// ---------------------------------------------------------------------------
// Kernel A: cylinder grouping, smem-staged points + software-pipelined LDS
// (prefetch iter ii+1's point while processing ii -> hides 29-cyc LDS chain).
// ---------------------------------------------------------------------------
#define GCHUNK 2048
#define GBUF (GCHUNK * 3)
__global__ __launch_bounds__(256) void group_kernel(
    const float* __restrict__ seed, const float* __restrict__ pc,
    const float* __restrict__ rot)
{
    extern __shared__ float gs[];
    int t = threadIdx.x, wid = t >> 5, lane = t & 31;
    int gw = blockIdx.x * 8 + wid;
    int b = gw >> 10;

    const float* sd = seed + (size_t)gw * 3;
    float sx = sd[0], sy = sd[1], sz = sd[2];
    const float* R = rot + (size_t)gw * 9;
    float r00 = R[0], r01 = R[1], r02 = R[2];
    float r10 = R[3], r11 = R[4], r12 = R[5];
    float r20 = R[6], r21 = R[7], r22 = R[8];
    const float* P = pc + (size_t)b * NPTS * 3;

    #pragma unroll
    for (int q = 0; q < 6; ++q)
        cpasync16(gs + (q * 256 + t) * 4, P + (q * 256 + t) * 4);
    cpcommit();

    int cnt[4] = {0, 0, 0, 0};
    float fx[4], fy[4], fz[4];
    float p0x = 0.f, p0y = 0.f, p0z = 0.f;
    const float hmax[4] = {0.1f, 0.2f, 0.3f, 0.4f};
    float* fb = g_feat + (size_t)gw * NDEPTH * NSAMP * 3;
    unsigned below = (1u << lane) - 1u;

    for (int c = 0; c < NPTS / GCHUNK; ++c) {
        asm volatile("cp.async.wait_group 0;");
        __syncthreads();
        if (c + 1 < NPTS / GCHUNK) {
            const float* src = P + (size_t)(c + 1) * GBUF;
            float* dst = gs + ((c + 1) & 1) * GBUF;
            #pragma unroll
            for (int q = 0; q < 6; ++q)
                cpasync16(dst + (q * 256 + t) * 4, src + (q * 256 + t) * 4);
            cpcommit();
        }
        const float* S = gs + (c & 1) * GBUF;
        // software pipeline: preload point for ii=0
        float cx = S[lane * 3 + 0], cy = S[lane * 3 + 1], cz = S[lane * 3 + 2];
        for (int ii = 0; ii < GCHUNK / 32; ++ii) {
            float nx = 0.f, ny = 0.f, nz = 0.f;
            if (ii + 1 < GCHUNK / 32) {
                int ni = (ii + 1) * 32 + lane;
                nx = S[ni * 3 + 0]; ny = S[ni * 3 + 1]; nz = S[ni * 3 + 2];
            }
            float rx = cx - sx, ry = cy - sy, rz = cz - sz;
            float ax = rx * r00 + ry * r10 + rz * r20;
            float ay = rx * r01 + ry * r11 + rz * r21;
            float az = rx * r02 + ry * r12 + rz * r22;
            float rr = ay * ay + az * az;
            if (c == 0 && ii == 0) {
                p0x = __shfl_sync(0xffffffffu, ax, 0);
                p0y = __shfl_sync(0xffffffffu, ay, 0);
                p0z = __shfl_sync(0xffffffffu, az, 0);
            }
            bool m3 = (ax > -0.2f) && (ax < 0.4f) && (rr < 0.09f);
            unsigned bal3 = __ballot_sync(0xffffffffu, m3);
            if (bal3) {
                #pragma unroll
                for (int d = 0; d < 4; ++d) {
                    bool m = m3 && (ax < hmax[d]);
                    unsigned bal = (d == 3) ? bal3 : __ballot_sync(0xffffffffu, m);
                    if (bal) {
                        if (cnt[d] == 0) {
                            int src = __ffs(bal) - 1;
                            fx[d] = __shfl_sync(0xffffffffu, ax, src);
                            fy[d] = __shfl_sync(0xffffffffu, ay, src);
                            fz[d] = __shfl_sync(0xffffffffu, az, src);
                        }
                        int pos = cnt[d] + __popc(bal & below);
                        if (m && pos < NSAMP) {
                            float* o = fb + ((size_t)d * NSAMP + pos) * 3;
                            o[0] = ax; o[1] = ay; o[2] = az;
                        }
                        cnt[d] += __popc(bal);
                    }
                }
            }
            cx = nx; cy = ny; cz = nz;
        }
    }
    #pragma unroll
    for (int d = 0; d < 4; ++d) {
        if (cnt[d] < NSAMP) {
            float vx, vy, vz;
            if (cnt[d] > 0) { vx = fx[d]; vy = fy[d]; vz = fz[d]; }
            else           { vx = p0x;   vy = p0y;   vz = p0z;   }
            for (int pos = cnt[d] + lane; pos < NSAMP; pos += 32) {
                float* o = fb + ((size_t)d * NSAMP + pos) * 3;
                o[0] = vx; o[1] = vy; o[2] = vz;
            }
        }
    }
}

// ---------------------------------------------------------------------------
// Kernel B: unchanged from round 11 (passing, 370us, near HMMA floor).
// ---------------------------------------------------------------------------
#define FSC1 0
#define FSH1 64
#define FSC2 128
#define FSH2 256
#define FSC3 384
#define FSH3 640
#define FW1  896
#define FFEAT 1088     // 384 floats
#define FRBMAX 1472    // 4 x 64
#define FRBMIN 1728    // 4 x 64
// byte offsets
#define SB_A2 8192u    // 128 x 272B = 34816
#define SB_B2 43008u   // 128 x 272B = 34816
#define SB_A3 8192u    // 128 x 528B = 67584 (over A2/B2, written after sync)
#define SB_B3Q0 77824u // 32 x 528B = 16896
#define SB_B3Q1 94720u
#define SMEM_B_BYTES 111616

__global__ __launch_bounds__(256, 2) void mlp_kernel(
    const float* __restrict__ cw1, const float* __restrict__ cbn1,
    const float* __restrict__ cbn2, const float* __restrict__ cbn3)
{
    extern __shared__ float sm[];
    char* smc = (char*)sm;
    int t = threadIdx.x, wid = t >> 5, lane = t & 31;
    int g0 = blockIdx.x * 2;
    unsigned sb = (unsigned)__cvta_generic_to_shared(sm);
    int mw = wid >> 1, nw = wid & 1;   // mw 0..3 (M), nw 0..1 (N)

    // stage: B2, then W3 pair0 (Q0+Q1 contiguous)
    #pragma unroll
    for (int q = 0; q < 9; ++q) {
        int e = q * 256 + t;
        if (e < 2176) cpasync16(smc + SB_B2 + e * 16, (const char*)g_w2p + e * 16);
    }
    cpcommit();
    #pragma unroll
    for (int q = 0; q < 9; ++q) {
        int e = q * 256 + t;
        if (e < 2112) cpasync16(smc + SB_B3Q0 + e * 16, (const char*)g_w3p + e * 16);
    }
    cpcommit();

    // consts + w1 + feat (2 groups)
    if (t < 64) {
        float sc = cbn1[t] * rsqrtf(cbn1[192 + t] + 1e-5f);
        sm[FSC1 + t] = sc; sm[FSH1 + t] = cbn1[64 + t] - cbn1[128 + t] * sc;
    }
    if (t < 128) {
        float sc = cbn2[t] * rsqrtf(cbn2[384 + t] + 1e-5f);
        sm[FSC2 + t] = sc; sm[FSH2 + t] = cbn2[128 + t] - cbn2[256 + t] * sc;
    }
    {
        float sc = cbn3[t] * rsqrtf(cbn3[768 + t] + 1e-5f);
        sm[FSC3 + t] = sc; sm[FSH3 + t] = cbn3[256 + t] - cbn3[512 + t] * sc;
    }
    if (t < 192) sm[FW1 + t] = cw1[t];
    for (int idx = t; idx < 384; idx += 256)
        sm[FFEAT + idx] = g_feat[(size_t)g0 * 192 + idx];
    __syncthreads();

    // --- Layer 1 ---
    #pragma unroll
    for (int q = 0; q < 32; ++q) {
        int o = q * 256 + t;
        int s = o >> 6, j = o & 63;
        const float* f = sm + FFEAT + s * 3;
        float x = f[0] * sm[FW1 + j * 3 + 0]
                + f[1] * sm[FW1 + j * 3 + 1]
                + f[2] * sm[FW1 + j * 3 + 2];
        x = fmaxf(x * sm[FSC1 + j] + sm[FSH1 + j], 0.f);
        __nv_bfloat16 hi = __float2bfloat16(x);
        __nv_bfloat16 lo = __float2bfloat16(x - __bfloat162float(hi));
        *(__nv_bfloat16*)(smc + SB_A2 + s * 272 + 2 * j) = hi;
        *(__nv_bfloat16*)(smc + SB_A2 + s * 272 + 128 + 2 * j) = lo;
    }
    asm volatile("cp.async.wait_group 1;");   // B2 resident
    __syncthreads();

    // --- Layer 2: M128 x N128 x K64 HMMA ---
    {
        float acc[2][8][4];
        #pragma unroll
        for (int m = 0; m < 2; ++m)
            #pragma unroll
            for (int g = 0; g < 8; ++g)
                #pragma unroll
                for (int c = 0; c < 4; ++c) acc[m][g][c] = 0.f;
        mma_block_n64<4, 272, 272, 128>(sb + SB_A2 + mw * 32 * 272,
                                        sb + SB_B2 + nw * 64 * 272, acc);
        __syncthreads();

        int r0b = mw * 32 + (lane >> 2);
        int j0b = nw * 64 + 2 * (lane & 3);
        #pragma unroll
        for (int m = 0; m < 2; ++m)
            #pragma unroll
            for (int g = 0; g < 8; ++g) {
                int j0 = j0b + g * 8;
                float sc0 = sm[FSC2 + j0], sh0 = sm[FSH2 + j0];
                float sc1 = sm[FSC2 + j0 + 1], sh1 = sm[FSH2 + j0 + 1];
                #pragma unroll
                for (int rh = 0; rh < 2; ++rh) {
                    int s = r0b + m * 16 + rh * 8;
                    float x0 = fmaxf(acc[m][g][2 * rh + 0] * sc0 + sh0, 0.f);
                    float x1 = fmaxf(acc[m][g][2 * rh + 1] * sc1 + sh1, 0.f);
                    __nv_bfloat162 h, l;
                    h.x = __float2bfloat16(x0);
                    h.y = __float2bfloat16(x1);
                    l.x = __float2bfloat16(x0 - __bfloat162float(h.x));
                    l.y = __float2bfloat16(x1 - __bfloat162float(h.y));
                    *(__nv_bfloat162*)(smc + SB_A3 + s * 528 + 2 * j0) = h;
                    *(__nv_bfloat162*)(smc + SB_A3 + s * 528 + 256 + 2 * j0) = l;
                }
            }
    }
    __syncthreads();

    // --- Layer 3: 4 quarter-PAIRS ---
    #pragma unroll 1
    for (int p = 0; p < 4; ++p) {
        asm volatile("cp.async.wait_group 0;");
        __syncthreads();

        float acc[2][2][2][4];
        #pragma unroll
        for (int b = 0; b < 2; ++b)
            #pragma unroll
            for (int m = 0; m < 2; ++m)
                #pragma unroll
                for (int g = 0; g < 2; ++g)
                    #pragma unroll
                    for (int c = 0; c < 4; ++c) acc[b][m][g][c] = 0.f;
        mma_block_n16_pair<8, 528, 528, 256>(
            sb + SB_A3 + mw * 32 * 528,
            sb + SB_B3Q0 + nw * 16 * 528,
            sb + SB_B3Q1 + nw * 16 * 528, acc);

        #pragma unroll
        for (int b = 0; b < 2; ++b)
            #pragma unroll
            for (int g = 0; g < 2; ++g) {
                float mx0 = -1e30f, mn0 = 1e30f, mx1 = -1e30f, mn1 = 1e30f;
                #pragma unroll
                for (int m = 0; m < 2; ++m)
                    #pragma unroll
                    for (int rh = 0; rh < 2; ++rh) {
                        float v0 = acc[b][m][g][2 * rh + 0], v1 = acc[b][m][g][2 * rh + 1];
                        mx0 = fmaxf(mx0, v0); mn0 = fminf(mn0, v0);
                        mx1 = fmaxf(mx1, v1); mn1 = fminf(mn1, v1);
                    }
                #pragma unroll
                for (int off = 4; off <= 16; off <<= 1) {
                    mx0 = fmaxf(mx0, __shfl_xor_sync(0xffffffffu, mx0, off));
                    mn0 = fminf(mn0, __shfl_xor_sync(0xffffffffu, mn0, off));
                    mx1 = fmaxf(mx1, __shfl_xor_sync(0xffffffffu, mx1, off));
                    mn1 = fminf(mn1, __shfl_xor_sync(0xffffffffu, mn1, off));
                }
                if ((lane >> 2) == 0) {
                    int chl = b * 32 + nw * 16 + g * 8 + 2 * (lane & 3);
                    sm[FRBMAX + mw * 64 + chl] = mx0;
                    sm[FRBMAX + mw * 64 + chl + 1] = mx1;
                    sm[FRBMIN + mw * 64 + chl] = mn0;
                    sm[FRBMIN + mw * 64 + chl + 1] = mn1;
                }
            }
        __syncthreads();

        if (t < 128) {
            int g = t >> 6, c64 = t & 63;
            float mx = fmaxf(sm[FRBMAX + 2 * g * 64 + c64], sm[FRBMAX + (2 * g + 1) * 64 + c64]);
            float mn = fminf(sm[FRBMIN + 2 * g * 64 + c64], sm[FRBMIN + (2 * g + 1) * 64 + c64]);
            int j = p * 64 + c64;
            float sc = sm[FSC3 + j], sh = sm[FSH3 + j];
            float val = (sc >= 0.f) ? sc * mx + sh : sc * mn + sh;
            g_vp[(size_t)(g0 + g) * 256 + j] = fmaxf(val, 0.f);
        }
        if (p < 3) {
            char* dst = smc + SB_B3Q0;
            const char* src = (const char*)g_w3p + (2 * p + 2) * 16896;
            #pragma unroll
            for (int qq = 0; qq < 9; ++qq) {
                int e = qq * 256 + t;
                if (e < 2112) cpasync16(dst + e * 16, src + e * 16);
            }
            cpcommit();
        }
    }
}

// ---------------------------------------------------------------------------
// Kernel C: both heads, rows=4 per block (512 blocks), no s_w3 stage
// (L3 weights read from L2-hot gmem) -> 51.2KB smem -> 4 CTAs/SM.
// ---------------------------------------------------------------------------
#define SMEM_C_FLOATS (1024*3 + 1024 + 256*34)
#define SMEM_C_BYTES  (SMEM_C_FLOATS * 4)   // 51200

__global__ __launch_bounds__(256) void head_kernel(
    const float* __restrict__ ow1, const float* __restrict__ ob1, const float* __restrict__ obn1,
    const float* __restrict__ ow2, const float* __restrict__ ob2, const float* __restrict__ obn2,
    const float* __restrict__ ow3, const float* __restrict__ ob3,
    const float* __restrict__ tw1, const float* __restrict__ tb1, const float* __restrict__ tbn1,
    const float* __restrict__ tw2, const float* __restrict__ tb2, const float* __restrict__ tbn2,
    const float* __restrict__ tw3, const float* __restrict__ tb3,
    float* __restrict__ out)
{
    extern __shared__ float sm[];
    float* s_vp = sm;              // 4 x 256
    float* s_h1 = s_vp + 1024;     // 4 x 256
    float* s_h2 = s_h1 + 1024;     // 4 x 256
    float* sA1  = s_h2 + 1024;
    float* hA1  = sA1 + 256;
    float* sA2  = hA1 + 256;
    float* hA2  = sA2 + 256;
    float* s_wt = hA2 + 256;       // 256 x 34

    int t = threadIdx.x;
    int row0 = blockIdx.x * 4;

    {
        int c = t & 127;
        if (t < 128) {
            float sc = obn1[c] * rsqrtf(obn1[384 + c] + 1e-5f);
            sA1[t] = sc; hA1[t] = (ob1[c] - obn1[256 + c]) * sc + obn1[128 + c];
            float s2 = obn2[c] * rsqrtf(obn2[384 + c] + 1e-5f);
            sA2[t] = s2; hA2[t] = (ob2[c] - obn2[256 + c]) * s2 + obn2[128 + c];
        } else {
            float sc = tbn1[c] * rsqrtf(tbn1[384 + c] + 1e-5f);
            sA1[t] = sc; hA1[t] = (tb1[c] - tbn1[256 + c]) * sc + tbn1[128 + c];
            float s2 = tbn2[c] * rsqrtf(tbn2[384 + c] + 1e-5f);
            sA2[t] = s2; hA2[t] = (tb2[c] - tbn2[256 + c]) * s2 + tbn2[128 + c];
        }
    }
    for (int idx = t; idx < 1024; idx += 256)
        s_vp[idx] = g_vp[(size_t)row0 * 256 + idx];
    __syncthreads();

    ull acc2[4];
    // Layer 1 (256 -> 128 per head)
    #pragma unroll
    for (int r = 0; r < 4; ++r) acc2[r] = 0ull;
    for (int i0 = 0; i0 < 256; i0 += 32) {
        #pragma unroll
        for (int q = 0; q < 32; ++q) {
            int idx = q * 256 + t; int r = idx >> 5, c = idx & 31;
            s_wt[r * 34 + c] = (r < 128) ? ow1[r * 256 + i0 + c]
                                         : tw1[(r - 128) * 256 + i0 + c];
        }
        __syncthreads();
        #pragma unroll
        for (int p = 0; p < 16; ++p) {
            ull w = *(const ull*)(s_wt + t * 34 + 2 * p);
            #pragma unroll
            for (int r = 0; r < 4; ++r) {
                ull a = *(const ull*)(s_vp + r * 256 + i0 + 2 * p);
                fma2(acc2[r], a, w);
            }
        }
        __syncthreads();
    }
    #pragma unroll
    for (int r = 0; r < 4; ++r)
        s_h1[r * 256 + t] = fmaxf(hsum2(acc2[r]) * sA1[t] + hA1[t], 0.f);
    __syncthreads();

    // Layer 2 (128 -> 128 per head)
    #pragma unroll
    for (int r = 0; r < 4; ++r) acc2[r] = 0ull;
    int hbase = t & 128;
    for (int i0 = 0; i0 < 128; i0 += 32) {
        #pragma unroll
        for (int q = 0; q < 32; ++q) {
            int idx = q * 256 + t; int r = idx >> 5, c = idx & 31;
            s_wt[r * 34 + c] = (r < 128) ? ow2[r * 128 + i0 + c]
                                         : tw2[(r - 128) * 128 + i0 + c];
        }
        __syncthreads();
        #pragma unroll
        for (int p = 0; p < 16; ++p) {
            ull w = *(const ull*)(s_wt + t * 34 + 2 * p);
            #pragma unroll
            for (int r = 0; r < 4; ++r) {
                ull a = *(const ull*)(s_h1 + r * 256 + hbase + i0 + 2 * p);
                fma2(acc2[r], a, w);
            }
        }
        __syncthreads();
    }
    #pragma unroll
    for (int r = 0; r < 4; ++r)
        s_h2[r * 256 + t] = fmaxf(hsum2(acc2[r]) * sA2[t] + hA2[t], 0.f);
    __syncthreads();

    // Layer 3 (128 -> 36|12): weights straight from gmem (L2-hot), 64 thr/row
    {
        int r = t >> 6, cc = t & 63;
        if (cc < 48) {
            const float* wsrc = (cc < 36) ? (ow3 + cc * 128) : (tw3 + (cc - 36) * 128);
            int hb = (cc < 36) ? 0 : 128;
            ull a2 = 0ull;
            #pragma unroll 8
            for (int p = 0; p < 64; ++p) {
                ull a = *(const ull*)(s_h2 + r * 256 + hb + 2 * p);
                ull w = *(const ull*)(wsrc + 2 * p);
                fma2(a2, a, w);
            }
            float a = hsum2(a2) + ((cc < 36) ? ob3[cc] : tb3[cc - 36]);
            int row = row0 + r;
            int b = row >> 12, rr = row & 4095, s = rr >> 2, d = rr & 3;
            out[(((size_t)b * 48 + cc) * 1024 + s) * 4 + d] = a;
        }
    }
}

// ---------------------------------------------------------------------------
extern "C" void kernel_launch(void* const* d_in, const int* in_sizes, int n_in,
                              void* d_out, int out_size)
{
    (void)in_sizes; (void)n_in; (void)out_size;
    const float* seed = (const float*)d_in[0];
    const float* pc   = (const float*)d_in[1];
    const float* rot  = (const float*)d_in[2];
    const float* cw1  = (const float*)d_in[3];
    const float* cbn1 = (const float*)d_in[4];
    const float* cw2  = (const float*)d_in[5];
    const float* cbn2 = (const float*)d_in[6];
    const float* cw3  = (const float*)d_in[7];
    const float* cbn3 = (const float*)d_in[8];
    const float* ow1  = (const float*)d_in[9];
    const float* ob1  = (const float*)d_in[10];
    const float* obn1 = (const float*)d_in[11];
    const float* ow2  = (const float*)d_in[12];
    const float* ob2  = (const float*)d_in[13];
    const float* obn2 = (const float*)d_in[14];
    const float* ow3  = (const float*)d_in[15];
    const float* ob3  = (const float*)d_in[16];
    const float* tw1  = (const float*)d_in[17];
    const float* tb1  = (const float*)d_in[18];
    const float* tbn1 = (const float*)d_in[19];
    const float* tw2  = (const float*)d_in[20];
    const float* tb2  = (const float*)d_in[21];
    const float* tbn2 = (const float*)d_in[22];
    const float* tw3  = (const float*)d_in[23];
    const float* tb3  = (const float*)d_in[24];
    float* out = (float*)d_out;

    cudaFuncSetAttribute(group_kernel, cudaFuncAttributeMaxDynamicSharedMemorySize, 49152);
    cudaFuncSetAttribute(mlp_kernel,  cudaFuncAttributeMaxDynamicSharedMemorySize, SMEM_B_BYTES);
    cudaFuncSetAttribute(head_kernel, cudaFuncAttributeMaxDynamicSharedMemorySize, SMEM_C_BYTES);

    prep_w2<<<32, 256>>>(cw2);
    prep_w3<<<128, 256>>>(cw3);
    group_kernel<<<256, 256, 49152>>>(seed, pc, rot);
    mlp_kernel<<<NSEED * NDEPTH, 256, SMEM_B_BYTES>>>(cw1, cbn1, cbn2, cbn3);
    head_kernel<<<2 * NSEED * NDEPTH / 4, 256, SMEM_C_BYTES>>>(
        ow1, ob1, obn1, ow2, ob2, obn2, ow3, ob3,
        tw1, tb1, tbn1, tw2, tb2, tbn2, tw3, tb3, out);
}

// round 14
// speedup vs baseline: 1.2270x; 1.2270x over previous
#include <cuda_runtime.h>
#include <cuda_bf16.h>
#include <cstddef>

#define NSEED 1024
#define NPTS  8192
#define NSAMP 64
#define NDEPTH 4

typedef unsigned long long ull;

__device__ float g_feat[2 * NSEED * NDEPTH * NSAMP * 3];   // ~6.3 MB
__device__ float g_vp[2 * NSEED * NDEPTH * 256];           // ~8.4 MB
// pre-split bf16 weights (hi || lo along k), padded rows for ldmatrix
__device__ __align__(16) __nv_bfloat16 g_w2p[128 * 136];   // row 272B
__device__ __align__(16) __nv_bfloat16 g_w3p[256 * 264];   // row 528B

// ---------------- helpers ---------------------------------------------------
__device__ __forceinline__ void fma2(ull& d, ull a, ull b) {
    asm("fma.rn.f32x2 %0, %1, %2, %0;" : "+l"(d) : "l"(a), "l"(b));
}
__device__ __forceinline__ float hsum2(ull v) {
    float lo, hi; asm("mov.b64 {%0, %1}, %2;" : "=f"(lo), "=f"(hi) : "l"(v));
    return lo + hi;
}
__device__ __forceinline__ void cpasync16(void* sdst, const void* gsrc) {
    unsigned s = (unsigned)__cvta_generic_to_shared(sdst);
    asm volatile("cp.async.ca.shared.global [%0], [%1], 16;" :: "r"(s), "l"(gsrc));
}
__device__ __forceinline__ void cpcommit() { asm volatile("cp.async.commit_group;"); }

__device__ __forceinline__ void ldsm4(unsigned a, unsigned& r0, unsigned& r1,
                                      unsigned& r2, unsigned& r3) {
    asm volatile("ldmatrix.sync.aligned.m8n8.x4.shared.b16 {%0,%1,%2,%3}, [%4];"
                 : "=r"(r0), "=r"(r1), "=r"(r2), "=r"(r3) : "r"(a));
}
__device__ __forceinline__ void mma_bf16(float* c, const unsigned* a, unsigned b0, unsigned b1) {
    asm volatile("mma.sync.aligned.m16n8k16.row.col.f32.bf16.bf16.f32 "
                 "{%0,%1,%2,%3}, {%4,%5,%6,%7}, {%8,%9}, {%0,%1,%2,%3};"
                 : "+f"(c[0]), "+f"(c[1]), "+f"(c[2]), "+f"(c[3])
                 : "r"(a[0]), "r"(a[1]), "r"(a[2]), "r"(a[3]), "r"(b0), "r"(b1));
}

// Warp GEMM M32 x N64, K = NI*16, 3-term split.
template<int NI, int AS, int BS, int LO>
__device__ __forceinline__ void mma_block_n64(unsigned aB, unsigned bB, float (&acc)[2][8][4]) {
    int lane = threadIdx.x & 31;
    unsigned ar = aB + (lane & 15) * AS + (lane >> 4) * 16;
    unsigned br = bB + (lane & 15) * BS + (lane >> 4) * 16;
    #pragma unroll 1
    for (int i = 0; i < NI; ++i) {
        unsigned ah[2][4], al[2][4], bh[4][4], bl[4][4];
        ldsm4(ar + 32 * i,           ah[0][0], ah[0][1], ah[0][2], ah[0][3]);
        ldsm4(ar + 16 * AS + 32 * i, ah[1][0], ah[1][1], ah[1][2], ah[1][3]);
        #pragma unroll
        for (int g = 0; g < 4; ++g)
            ldsm4(br + g * (16 * BS) + 32 * i, bh[g][0], bh[g][1], bh[g][2], bh[g][3]);
        #pragma unroll
        for (int m = 0; m < 2; ++m)
            #pragma unroll
            for (int g = 0; g < 4; ++g) {
                mma_bf16(acc[m][2 * g + 0], ah[m], bh[g][0], bh[g][2]);
                mma_bf16(acc[m][2 * g + 1], ah[m], bh[g][1], bh[g][3]);
            }
        #pragma unroll
        for (int g = 0; g < 4; ++g)
            ldsm4(br + g * (16 * BS) + LO + 32 * i, bl[g][0], bl[g][1], bl[g][2], bl[g][3]);
        #pragma unroll
        for (int m = 0; m < 2; ++m)
            #pragma unroll
            for (int g = 0; g < 4; ++g) {
                mma_bf16(acc[m][2 * g + 0], ah[m], bl[g][0], bl[g][2]);
                mma_bf16(acc[m][2 * g + 1], ah[m], bl[g][1], bl[g][3]);
            }
        ldsm4(ar + LO + 32 * i,           al[0][0], al[0][1], al[0][2], al[0][3]);
        ldsm4(ar + 16 * AS + LO + 32 * i, al[1][0], al[1][1], al[1][2], al[1][3]);
        #pragma unroll
        for (int m = 0; m < 2; ++m)
            #pragma unroll
            for (int g = 0; g < 4; ++g) {
                mma_bf16(acc[m][2 * g + 0], al[m], bh[g][0], bh[g][2]);
                mma_bf16(acc[m][2 * g + 1], al[m], bh[g][1], bh[g][3]);
            }
    }
}

// Warp GEMM M32 x (2 x N16) over TWO quarter buffers sharing A-fragments:
// 8 ldsm feed 24 MMAs.
template<int NI, int AS, int BS, int LO>
__device__ __forceinline__ void mma_block_n16_pair(unsigned aB, unsigned b0B, unsigned b1B,
                                                   float (&acc)[2][2][2][4]) {
    int lane = threadIdx.x & 31;
    unsigned ar = aB + (lane & 15) * AS + (lane >> 4) * 16;
    unsigned br0 = b0B + (lane & 15) * BS + (lane >> 4) * 16;
    unsigned br1 = b1B + (lane & 15) * BS + (lane >> 4) * 16;
    #pragma unroll 1
    for (int i = 0; i < NI; ++i) {
        unsigned ah[2][4], al[2][4], bh[2][4], bl[2][4];
        ldsm4(ar + 32 * i,                ah[0][0], ah[0][1], ah[0][2], ah[0][3]);
        ldsm4(ar + 16 * AS + 32 * i,      ah[1][0], ah[1][1], ah[1][2], ah[1][3]);
        ldsm4(ar + LO + 32 * i,           al[0][0], al[0][1], al[0][2], al[0][3]);
        ldsm4(ar + 16 * AS + LO + 32 * i, al[1][0], al[1][1], al[1][2], al[1][3]);
        ldsm4(br0 + 32 * i,      bh[0][0], bh[0][1], bh[0][2], bh[0][3]);
        ldsm4(br0 + LO + 32 * i, bl[0][0], bl[0][1], bl[0][2], bl[0][3]);
        ldsm4(br1 + 32 * i,      bh[1][0], bh[1][1], bh[1][2], bh[1][3]);
        ldsm4(br1 + LO + 32 * i, bl[1][0], bl[1][1], bl[1][2], bl[1][3]);
        #pragma unroll
        for (int b = 0; b < 2; ++b)
            #pragma unroll
            for (int m = 0; m < 2; ++m) {
                mma_bf16(acc[b][m][0], ah[m], bh[b][0], bh[b][2]);
                mma_bf16(acc[b][m][1], ah[m], bh[b][1], bh[b][3]);
                mma_bf16(acc[b][m][0], ah[m], bl[b][0], bl[b][2]);
                mma_bf16(acc[b][m][1], ah[m], bl[b][1], bl[b][3]);
                mma_bf16(acc[b][m][0], al[m], bh[b][0], bh[b][2]);
                mma_bf16(acc[b][m][1], al[m], bh[b][1], bh[b][3]);
            }
    }
}

// ---------------------------------------------------------------------------
// Prep: split W2/W3 into bf16 hi/lo padded rows.
// ---------------------------------------------------------------------------
__global__ void prep_w2(const float* __restrict__ cw2) {
    int idx = blockIdx.x * 256 + threadIdx.x;   // 128 x 64
    if (idx >= 128 * 64) return;
    int j = idx >> 6, k = idx & 63;
    float w = cw2[idx];
    __nv_bfloat16 hi = __float2bfloat16(w);
    __nv_bfloat16 lo = __float2bfloat16(w - __bfloat162float(hi));
    g_w2p[j * 136 + k] = hi;
    g_w2p[j * 136 + 64 + k] = lo;
}
__global__ void prep_w3(const float* __restrict__ cw3) {
    int idx = blockIdx.x * 256 + threadIdx.x;   // 256 x 128
    if (idx >= 256 * 128) return;
    int j = idx >> 7, k = idx & 127;
    float w = cw3[idx];
    __nv_bfloat16 hi = __float2bfloat16(w);
    __nv_bfloat16 lo = __float2bfloat16(w - __bfloat162float(hi));
    g_w3p[j * 264 + k] = hi;
    g_w3p[j * 264 + 128 + k] = lo;
}

// ---------------------------------------------------------------------------
// Kernel A: cylinder grouping, smem-staged points + software-pipelined LDS.
// ---------------------------------------------------------------------------
#define GCHUNK 2048
#define GBUF (GCHUNK * 3)
__global__ __launch_bounds__(256) void group_kernel(
    const float* __restrict__ seed, const float* __restrict__ pc,
    const float* __restrict__ rot)
{
    extern __shared__ float gs[];
    int t = threadIdx.x, wid = t >> 5, lane = t & 31;
    int gw = blockIdx.x * 8 + wid;
    int b = gw >> 10;

    const float* sd = seed + (size_t)gw * 3;
    float sx = sd[0], sy = sd[1], sz = sd[2];
    const float* R = rot + (size_t)gw * 9;
    float r00 = R[0], r01 = R[1], r02 = R[2];
    float r10 = R[3], r11 = R[4], r12 = R[5];
    float r20 = R[6], r21 = R[7], r22 = R[8];
    const float* P = pc + (size_t)b * NPTS * 3;

    #pragma unroll
    for (int q = 0; q < 6; ++q)
        cpasync16(gs + (q * 256 + t) * 4, P + (q * 256 + t) * 4);
    cpcommit();

    int cnt[4] = {0, 0, 0, 0};
    float fx[4], fy[4], fz[4];
    float p0x = 0.f, p0y = 0.f, p0z = 0.f;
    const float hmax[4] = {0.1f, 0.2f, 0.3f, 0.4f};
    float* fb = g_feat + (size_t)gw * NDEPTH * NSAMP * 3;
    unsigned below = (1u << lane) - 1u;

    for (int c = 0; c < NPTS / GCHUNK; ++c) {
        asm volatile("cp.async.wait_group 0;");
        __syncthreads();
        if (c + 1 < NPTS / GCHUNK) {
            const float* src = P + (size_t)(c + 1) * GBUF;
            float* dst = gs + ((c + 1) & 1) * GBUF;
            #pragma unroll
            for (int q = 0; q < 6; ++q)
                cpasync16(dst + (q * 256 + t) * 4, src + (q * 256 + t) * 4);
            cpcommit();
        }
        const float* S = gs + (c & 1) * GBUF;
        float cx = S[lane * 3 + 0], cy = S[lane * 3 + 1], cz = S[lane * 3 + 2];
        for (int ii = 0; ii < GCHUNK / 32; ++ii) {
            float nx = 0.f, ny = 0.f, nz = 0.f;
            if (ii + 1 < GCHUNK / 32) {
                int ni = (ii + 1) * 32 + lane;
                nx = S[ni * 3 + 0]; ny = S[ni * 3 + 1]; nz = S[ni * 3 + 2];
            }
            float rx = cx - sx, ry = cy - sy, rz = cz - sz;
            float ax = rx * r00 + ry * r10 + rz * r20;
            float ay = rx * r01 + ry * r11 + rz * r21;
            float az = rx * r02 + ry * r12 + rz * r22;
            float rr = ay * ay + az * az;
            if (c == 0 && ii == 0) {
                p0x = __shfl_sync(0xffffffffu, ax, 0);
                p0y = __shfl_sync(0xffffffffu, ay, 0);
                p0z = __shfl_sync(0xffffffffu, az, 0);
            }
            bool m3 = (ax > -0.2f) && (ax < 0.4f) && (rr < 0.09f);
            unsigned bal3 = __ballot_sync(0xffffffffu, m3);
            if (bal3) {
                #pragma unroll
                for (int d = 0; d < 4; ++d) {
                    bool m = m3 && (ax < hmax[d]);
                    unsigned bal = (d == 3) ? bal3 : __ballot_sync(0xffffffffu, m);
                    if (bal) {
                        if (cnt[d] == 0) {
                            int src = __ffs(bal) - 1;
                            fx[d] = __shfl_sync(0xffffffffu, ax, src);
                            fy[d] = __shfl_sync(0xffffffffu, ay, src);
                            fz[d] = __shfl_sync(0xffffffffu, az, src);
                        }
                        int pos = cnt[d] + __popc(bal & below);
                        if (m && pos < NSAMP) {
                            float* o = fb + ((size_t)d * NSAMP + pos) * 3;
                            o[0] = ax; o[1] = ay; o[2] = az;
                        }
                        cnt[d] += __popc(bal);
                    }
                }
            }
            cx = nx; cy = ny; cz = nz;
        }
    }
    #pragma unroll
    for (int d = 0; d < 4; ++d) {
        if (cnt[d] < NSAMP) {
            float vx, vy, vz;
            if (cnt[d] > 0) { vx = fx[d]; vy = fy[d]; vz = fz[d]; }
            else           { vx = p0x;   vy = p0y;   vz = p0z;   }
            for (int pos = cnt[d] + lane; pos < NSAMP; pos += 32) {
                float* o = fb + ((size_t)d * NSAMP + pos) * 3;
                o[0] = vx; o[1] = vy; o[2] = vz;
            }
        }
    }
}

// ---------------------------------------------------------------------------
// Kernel B: unchanged (passing, ~369us, near HMMA floor for this design).
// ---------------------------------------------------------------------------
#define FSC1 0
#define FSH1 64
#define FSC2 128
#define FSH2 256
#define FSC3 384
#define FSH3 640
#define FW1  896
#define FFEAT 1088     // 384 floats
#define FRBMAX 1472    // 4 x 64
#define FRBMIN 1728    // 4 x 64
// byte offsets
#define SB_A2 8192u    // 128 x 272B = 34816
#define SB_B2 43008u   // 128 x 272B = 34816
#define SB_A3 8192u    // 128 x 528B = 67584 (over A2/B2, written after sync)
#define SB_B3Q0 77824u // 32 x 528B = 16896
#define SB_B3Q1 94720u
#define SMEM_B_BYTES 111616

__global__ __launch_bounds__(256, 2) void mlp_kernel(
    const float* __restrict__ cw1, const float* __restrict__ cbn1,
    const float* __restrict__ cbn2, const float* __restrict__ cbn3)
{
    extern __shared__ float sm[];
    char* smc = (char*)sm;
    int t = threadIdx.x, wid = t >> 5, lane = t & 31;
    int g0 = blockIdx.x * 2;
    unsigned sb = (unsigned)__cvta_generic_to_shared(sm);
    int mw = wid >> 1, nw = wid & 1;   // mw 0..3 (M), nw 0..1 (N)

    // stage: B2, then W3 pair0 (Q0+Q1 contiguous)
    #pragma unroll
    for (int q = 0; q < 9; ++q) {
        int e = q * 256 + t;
        if (e < 2176) cpasync16(smc + SB_B2 + e * 16, (const char*)g_w2p + e * 16);
    }
    cpcommit();
    #pragma unroll
    for (int q = 0; q < 9; ++q) {
        int e = q * 256 + t;
        if (e < 2112) cpasync16(smc + SB_B3Q0 + e * 16, (const char*)g_w3p + e * 16);
    }
    cpcommit();

    // consts + w1 + feat (2 groups)
    if (t < 64) {
        float sc = cbn1[t] * rsqrtf(cbn1[192 + t] + 1e-5f);
        sm[FSC1 + t] = sc; sm[FSH1 + t] = cbn1[64 + t] - cbn1[128 + t] * sc;
    }
    if (t < 128) {
        float sc = cbn2[t] * rsqrtf(cbn2[384 + t] + 1e-5f);
        sm[FSC2 + t] = sc; sm[FSH2 + t] = cbn2[128 + t] - cbn2[256 + t] * sc;
    }
    {
        float sc = cbn3[t] * rsqrtf(cbn3[768 + t] + 1e-5f);
        sm[FSC3 + t] = sc; sm[FSH3 + t] = cbn3[256 + t] - cbn3[512 + t] * sc;
    }
    if (t < 192) sm[FW1 + t] = cw1[t];
    for (int idx = t; idx < 384; idx += 256)
        sm[FFEAT + idx] = g_feat[(size_t)g0 * 192 + idx];
    __syncthreads();

    // --- Layer 1 ---
    #pragma unroll
    for (int q = 0; q < 32; ++q) {
        int o = q * 256 + t;
        int s = o >> 6, j = o & 63;
        const float* f = sm + FFEAT + s * 3;
        float x = f[0] * sm[FW1 + j * 3 + 0]
                + f[1] * sm[FW1 + j * 3 + 1]
                + f[2] * sm[FW1 + j * 3 + 2];
        x = fmaxf(x * sm[FSC1 + j] + sm[FSH1 + j], 0.f);
        __nv_bfloat16 hi = __float2bfloat16(x);
        __nv_bfloat16 lo = __float2bfloat16(x - __bfloat162float(hi));
        *(__nv_bfloat16*)(smc + SB_A2 + s * 272 + 2 * j) = hi;
        *(__nv_bfloat16*)(smc + SB_A2 + s * 272 + 128 + 2 * j) = lo;
    }
    asm volatile("cp.async.wait_group 1;");   // B2 resident
    __syncthreads();

    // --- Layer 2: M128 x N128 x K64 HMMA ---
    {
        float acc[2][8][4];
        #pragma unroll
        for (int m = 0; m < 2; ++m)
            #pragma unroll
            for (int g = 0; g < 8; ++g)
                #pragma unroll
                for (int c = 0; c < 4; ++c) acc[m][g][c] = 0.f;
        mma_block_n64<4, 272, 272, 128>(sb + SB_A2 + mw * 32 * 272,
                                        sb + SB_B2 + nw * 64 * 272, acc);
        __syncthreads();

        int r0b = mw * 32 + (lane >> 2);
        int j0b = nw * 64 + 2 * (lane & 3);
        #pragma unroll
        for (int m = 0; m < 2; ++m)
            #pragma unroll
            for (int g = 0; g < 8; ++g) {
                int j0 = j0b + g * 8;
                float sc0 = sm[FSC2 + j0], sh0 = sm[FSH2 + j0];
                float sc1 = sm[FSC2 + j0 + 1], sh1 = sm[FSH2 + j0 + 1];
                #pragma unroll
                for (int rh = 0; rh < 2; ++rh) {
                    int s = r0b + m * 16 + rh * 8;
                    float x0 = fmaxf(acc[m][g][2 * rh + 0] * sc0 + sh0, 0.f);
                    float x1 = fmaxf(acc[m][g][2 * rh + 1] * sc1 + sh1, 0.f);
                    __nv_bfloat162 h, l;
                    h.x = __float2bfloat16(x0);
                    h.y = __float2bfloat16(x1);
                    l.x = __float2bfloat16(x0 - __bfloat162float(h.x));
                    l.y = __float2bfloat16(x1 - __bfloat162float(h.y));
                    *(__nv_bfloat162*)(smc + SB_A3 + s * 528 + 2 * j0) = h;
                    *(__nv_bfloat162*)(smc + SB_A3 + s * 528 + 256 + 2 * j0) = l;
                }
            }
    }
    __syncthreads();

    // --- Layer 3: 4 quarter-PAIRS ---
    #pragma unroll 1
    for (int p = 0; p < 4; ++p) {
        asm volatile("cp.async.wait_group 0;");
        __syncthreads();

        float acc[2][2][2][4];
        #pragma unroll
        for (int b = 0; b < 2; ++b)
            #pragma unroll
            for (int m = 0; m < 2; ++m)
                #pragma unroll
                for (int g = 0; g < 2; ++g)
                    #pragma unroll
                    for (int c = 0; c < 4; ++c) acc[b][m][g][c] = 0.f;
        mma_block_n16_pair<8, 528, 528, 256>(
            sb + SB_A3 + mw * 32 * 528,
            sb + SB_B3Q0 + nw * 16 * 528,
            sb + SB_B3Q1 + nw * 16 * 528, acc);

        #pragma unroll
        for (int b = 0; b < 2; ++b)
            #pragma unroll
            for (int g = 0; g < 2; ++g) {
                float mx0 = -1e30f, mn0 = 1e30f, mx1 = -1e30f, mn1 = 1e30f;
                #pragma unroll
                for (int m = 0; m < 2; ++m)
                    #pragma unroll
                    for (int rh = 0; rh < 2; ++rh) {
                        float v0 = acc[b][m][g][2 * rh + 0], v1 = acc[b][m][g][2 * rh + 1];
                        mx0 = fmaxf(mx0, v0); mn0 = fminf(mn0, v0);
                        mx1 = fmaxf(mx1, v1); mn1 = fminf(mn1, v1);
                    }
                #pragma unroll
                for (int off = 4; off <= 16; off <<= 1) {
                    mx0 = fmaxf(mx0, __shfl_xor_sync(0xffffffffu, mx0, off));
                    mn0 = fminf(mn0, __shfl_xor_sync(0xffffffffu, mn0, off));
                    mx1 = fmaxf(mx1, __shfl_xor_sync(0xffffffffu, mx1, off));
                    mn1 = fminf(mn1, __shfl_xor_sync(0xffffffffu, mn1, off));
                }
                if ((lane >> 2) == 0) {
                    int chl = b * 32 + nw * 16 + g * 8 + 2 * (lane & 3);
                    sm[FRBMAX + mw * 64 + chl] = mx0;
                    sm[FRBMAX + mw * 64 + chl + 1] = mx1;
                    sm[FRBMIN + mw * 64 + chl] = mn0;
                    sm[FRBMIN + mw * 64 + chl + 1] = mn1;
                }
            }
        __syncthreads();

        if (t < 128) {
            int g = t >> 6, c64 = t & 63;
            float mx = fmaxf(sm[FRBMAX + 2 * g * 64 + c64], sm[FRBMAX + (2 * g + 1) * 64 + c64]);
            float mn = fminf(sm[FRBMIN + 2 * g * 64 + c64], sm[FRBMIN + (2 * g + 1) * 64 + c64]);
            int j = p * 64 + c64;
            float sc = sm[FSC3 + j], sh = sm[FSH3 + j];
            float val = (sc >= 0.f) ? sc * mx + sh : sc * mn + sh;
            g_vp[(size_t)(g0 + g) * 256 + j] = fmaxf(val, 0.f);
        }
        if (p < 3) {
            char* dst = smc + SB_B3Q0;
            const char* src = (const char*)g_w3p + (2 * p + 2) * 16896;
            #pragma unroll
            for (int qq = 0; qq < 9; ++qq) {
                int e = qq * 256 + t;
                if (e < 2112) cpasync16(dst + e * 16, src + e * 16);
            }
            cpcommit();
        }
    }
}

// ---------------------------------------------------------------------------
// Kernel C: both heads, 16 rows per block (512 blocks) — per-block weight
// staging amortized over 2x the rows vs round 11. s_w3 smem stage restored.
// ---------------------------------------------------------------------------
#define HR 16
#define SMEM_C_FLOATS (HR*256*3 + 256*4 + 256*34 + 48*130)
#define SMEM_C_BYTES  (SMEM_C_FLOATS * 4)   // 113024

__global__ __launch_bounds__(256) void head_kernel(
    const float* __restrict__ ow1, const float* __restrict__ ob1, const float* __restrict__ obn1,
    const float* __restrict__ ow2, const float* __restrict__ ob2, const float* __restrict__ obn2,
    const float* __restrict__ ow3, const float* __restrict__ ob3,
    const float* __restrict__ tw1, const float* __restrict__ tb1, const float* __restrict__ tbn1,
    const float* __restrict__ tw2, const float* __restrict__ tb2, const float* __restrict__ tbn2,
    const float* __restrict__ tw3, const float* __restrict__ tb3,
    float* __restrict__ out)
{
    extern __shared__ float sm[];
    float* s_vp = sm;                  // HR x 256
    float* s_h1 = s_vp + HR * 256;     // HR x 256
    float* s_h2 = s_h1 + HR * 256;     // HR x 256
    float* sA1  = s_h2 + HR * 256;
    float* hA1  = sA1 + 256;
    float* sA2  = hA1 + 256;
    float* hA2  = sA2 + 256;
    float* s_wt = hA2 + 256;           // 256 x 34
    float* s_w3 = s_wt + 256 * 34;     // 48 x 130

    int t = threadIdx.x;
    int row0 = blockIdx.x * HR;

    {
        int c = t & 127;
        if (t < 128) {
            float sc = obn1[c] * rsqrtf(obn1[384 + c] + 1e-5f);
            sA1[t] = sc; hA1[t] = (ob1[c] - obn1[256 + c]) * sc + obn1[128 + c];
            float s2 = obn2[c] * rsqrtf(obn2[384 + c] + 1e-5f);
            sA2[t] = s2; hA2[t] = (ob2[c] - obn2[256 + c]) * s2 + obn2[128 + c];
        } else {
            float sc = tbn1[c] * rsqrtf(tbn1[384 + c] + 1e-5f);
            sA1[t] = sc; hA1[t] = (tb1[c] - tbn1[256 + c]) * sc + tbn1[128 + c];
            float s2 = tbn2[c] * rsqrtf(tbn2[384 + c] + 1e-5f);
            sA2[t] = s2; hA2[t] = (tb2[c] - tbn2[256 + c]) * s2 + tbn2[128 + c];
        }
    }
    for (int idx = t; idx < HR * 256; idx += 256)
        s_vp[idx] = g_vp[(size_t)row0 * 256 + idx];
    for (int idx = t; idx < 48 * 128; idx += 256) {
        int r = idx >> 7, c = idx & 127;
        s_w3[r * 130 + c] = (r < 36) ? ow3[r * 128 + c] : tw3[(r - 36) * 128 + c];
    }
    __syncthreads();

    ull acc2[HR];
    // Layer 1 (256 -> 128 per head), channel = t, rows 0..HR-1
    #pragma unroll
    for (int r = 0; r < HR; ++r) acc2[r] = 0ull;
    for (int i0 = 0; i0 < 256; i0 += 32) {
        #pragma unroll
        for (int q = 0; q < 32; ++q) {
            int idx = q * 256 + t; int r = idx >> 5, c = idx & 31;
            s_wt[r * 34 + c] = (r < 128) ? ow1[r * 256 + i0 + c]
                                         : tw1[(r - 128) * 256 + i0 + c];
        }
        __syncthreads();
        #pragma unroll
        for (int p = 0; p < 16; ++p) {
            ull w = *(const ull*)(s_wt + t * 34 + 2 * p);
            #pragma unroll
            for (int r = 0; r < HR; ++r) {
                ull a = *(const ull*)(s_vp + r * 256 + i0 + 2 * p);   // warp-broadcast
                fma2(acc2[r], a, w);
            }
        }
        __syncthreads();
    }
    #pragma unroll
    for (int r = 0; r < HR; ++r)
        s_h1[r * 256 + t] = fmaxf(hsum2(acc2[r]) * sA1[t] + hA1[t], 0.f);
    __syncthreads();

    // Layer 2 (128 -> 128 per head)
    #pragma unroll
    for (int r = 0; r < HR; ++r) acc2[r] = 0ull;
    int hbase = t & 128;
    for (int i0 = 0; i0 < 128; i0 += 32) {
        #pragma unroll
        for (int q = 0; q < 32; ++q) {
            int idx = q * 256 + t; int r = idx >> 5, c = idx & 31;
            s_wt[r * 34 + c] = (r < 128) ? ow2[r * 128 + i0 + c]
                                         : tw2[(r - 128) * 128 + i0 + c];
        }
        __syncthreads();
        #pragma unroll
        for (int p = 0; p < 16; ++p) {
            ull w = *(const ull*)(s_wt + t * 34 + 2 * p);
            #pragma unroll
            for (int r = 0; r < HR; ++r) {
                ull a = *(const ull*)(s_h1 + r * 256 + hbase + i0 + 2 * p);
                fma2(acc2[r], a, w);
            }
        }
        __syncthreads();
    }
    #pragma unroll
    for (int r = 0; r < HR; ++r)
        s_h2[r * 256 + t] = fmaxf(hsum2(acc2[r]) * sA2[t] + hA2[t], 0.f);
    __syncthreads();

    // Layer 3 (128 -> 36|12): 16 threads/row, 3 channels each, transposed out
    {
        int r = t >> 4, c0 = t & 15;
        #pragma unroll
        for (int third = 0; third < 3; ++third) {
            int cc = c0 + third * 16;   // 0..47
            int hb = (cc < 36) ? 0 : 128;
            const float* wrow = s_w3 + cc * 130;
            ull a2 = 0ull;
            #pragma unroll 8
            for (int p = 0; p < 64; ++p) {
                ull a = *(const ull*)(s_h2 + r * 256 + hb + 2 * p);
                ull w = *(const ull*)(wrow + 2 * p);
                fma2(a2, a, w);
            }
            float a = hsum2(a2) + ((cc < 36) ? ob3[cc] : tb3[cc - 36]);
            int row = row0 + r;
            int b = row >> 12, rr = row & 4095, s = rr >> 2, d = rr & 3;
            out[(((size_t)b * 48 + cc) * 1024 + s) * 4 + d] = a;
        }
    }
}

// ---------------------------------------------------------------------------
extern "C" void kernel_launch(void* const* d_in, const int* in_sizes, int n_in,
                              void* d_out, int out_size)
{
    (void)in_sizes; (void)n_in; (void)out_size;
    const float* seed = (const float*)d_in[0];
    const float* pc   = (const float*)d_in[1];
    const float* rot  = (const float*)d_in[2];
    const float* cw1  = (const float*)d_in[3];
    const float* cbn1 = (const float*)d_in[4];
    const float* cw2  = (const float*)d_in[5];
    const float* cbn2 = (const float*)d_in[6];
    const float* cw3  = (const float*)d_in[7];
    const float* cbn3 = (const float*)d_in[8];
    const float* ow1  = (const float*)d_in[9];
    const float* ob1  = (const float*)d_in[10];
    const float* obn1 = (const float*)d_in[11];
    const float* ow2  = (const float*)d_in[12];
    const float* ob2  = (const float*)d_in[13];
    const float* obn2 = (const float*)d_in[14];
    const float* ow3  = (const float*)d_in[15];
    const float* ob3  = (const float*)d_in[16];
    const float* tw1  = (const float*)d_in[17];
    const float* tb1  = (const float*)d_in[18];
    const float* tbn1 = (const float*)d_in[19];
    const float* tw2  = (const float*)d_in[20];
    const float* tb2  = (const float*)d_in[21];
    const float* tbn2 = (const float*)d_in[22];
    const float* tw3  = (const float*)d_in[23];
    const float* tb3  = (const float*)d_in[24];
    float* out = (float*)d_out;

    cudaFuncSetAttribute(group_kernel, cudaFuncAttributeMaxDynamicSharedMemorySize, 49152);
    cudaFuncSetAttribute(mlp_kernel,  cudaFuncAttributeMaxDynamicSharedMemorySize, SMEM_B_BYTES);
    cudaFuncSetAttribute(head_kernel, cudaFuncAttributeMaxDynamicSharedMemorySize, SMEM_C_BYTES);

    prep_w2<<<32, 256>>>(cw2);
    prep_w3<<<128, 256>>>(cw3);
    group_kernel<<<256, 256, 49152>>>(seed, pc, rot);
    mlp_kernel<<<NSEED * NDEPTH, 256, SMEM_B_BYTES>>>(cw1, cbn1, cbn2, cbn3);
    head_kernel<<<2 * NSEED * NDEPTH / HR, 256, SMEM_C_BYTES>>>(
        ow1, ob1, obn1, ow2, ob2, obn2, ow3, ob3,
        tw1, tb1, tbn1, tw2, tb2, tbn2, tw3, tb3, out);
}

// round 15
// speedup vs baseline: 1.4784x; 1.2049x over previous
#include <cuda_runtime.h>
#include <cuda_fp16.h>
#include <cstddef>

#define NSEED 1024
#define NPTS  8192
#define NSAMP 64
#define NDEPTH 4

typedef unsigned long long ull;

__device__ float g_feat[2 * NSEED * NDEPTH * NSAMP * 3];   // ~6.3 MB
__device__ float g_vp[2 * NSEED * NDEPTH * 256];           // ~8.4 MB
// fp16 weights, hi || lo along k, padded rows for ldmatrix
__device__ __align__(16) __half g_w2p[128 * 136];   // row 272B: 64 hi, 64 lo, 8 pad
__device__ __align__(16) __half g_w3p[256 * 264];   // row 528B: 128 hi, 128 lo, 8 pad

// ---------------- helpers ---------------------------------------------------
__device__ __forceinline__ void fma2(ull& d, ull a, ull b) {
    asm("fma.rn.f32x2 %0, %1, %2, %0;" : "+l"(d) : "l"(a), "l"(b));
}
__device__ __forceinline__ float hsum2(ull v) {
    float lo, hi; asm("mov.b64 {%0, %1}, %2;" : "=f"(lo), "=f"(hi) : "l"(v));
    return lo + hi;
}
__device__ __forceinline__ void cpasync16(void* sdst, const void* gsrc) {
    unsigned s = (unsigned)__cvta_generic_to_shared(sdst);
    asm volatile("cp.async.ca.shared.global [%0], [%1], 16;" :: "r"(s), "l"(gsrc));
}
__device__ __forceinline__ void cpcommit() { asm volatile("cp.async.commit_group;"); }

__device__ __forceinline__ void ldsm4(unsigned a, unsigned& r0, unsigned& r1,
                                      unsigned& r2, unsigned& r3) {
    asm volatile("ldmatrix.sync.aligned.m8n8.x4.shared.b16 {%0,%1,%2,%3}, [%4];"
                 : "=r"(r0), "=r"(r1), "=r"(r2), "=r"(r3) : "r"(a));
}
__device__ __forceinline__ void mma_f16(float* c, const unsigned* a, unsigned b0, unsigned b1) {
    asm volatile("mma.sync.aligned.m16n8k16.row.col.f32.f16.f16.f32 "
                 "{%0,%1,%2,%3}, {%4,%5,%6,%7}, {%8,%9}, {%0,%1,%2,%3};"
                 : "+f"(c[0]), "+f"(c[1]), "+f"(c[2]), "+f"(c[3])
                 : "r"(a[0]), "r"(a[1]), "r"(a[2]), "r"(a[3]), "r"(b0), "r"(b1));
}

// Warp GEMM M32 x N64, K = NI*16, 2-term (A fp16 single, W fp16 hi+lo).
template<int NI, int AS, int BS, int LO>
__device__ __forceinline__ void mma_block_n64_2t(unsigned aB, unsigned bB, float (&acc)[2][8][4]) {
    int lane = threadIdx.x & 31;
    unsigned ar = aB + (lane & 15) * AS + (lane >> 4) * 16;
    unsigned br = bB + (lane & 15) * BS + (lane >> 4) * 16;
    #pragma unroll 1
    for (int i = 0; i < NI; ++i) {
        unsigned ah[2][4], bh[4][4], bl[4][4];
        ldsm4(ar + 32 * i,           ah[0][0], ah[0][1], ah[0][2], ah[0][3]);
        ldsm4(ar + 16 * AS + 32 * i, ah[1][0], ah[1][1], ah[1][2], ah[1][3]);
        #pragma unroll
        for (int g = 0; g < 4; ++g)
            ldsm4(br + g * (16 * BS) + 32 * i, bh[g][0], bh[g][1], bh[g][2], bh[g][3]);
        #pragma unroll
        for (int m = 0; m < 2; ++m)
            #pragma unroll
            for (int g = 0; g < 4; ++g) {
                mma_f16(acc[m][2 * g + 0], ah[m], bh[g][0], bh[g][2]);
                mma_f16(acc[m][2 * g + 1], ah[m], bh[g][1], bh[g][3]);
            }
        #pragma unroll
        for (int g = 0; g < 4; ++g)
            ldsm4(br + g * (16 * BS) + LO + 32 * i, bl[g][0], bl[g][1], bl[g][2], bl[g][3]);
        #pragma unroll
        for (int m = 0; m < 2; ++m)
            #pragma unroll
            for (int g = 0; g < 4; ++g) {
                mma_f16(acc[m][2 * g + 0], ah[m], bl[g][0], bl[g][2]);
                mma_f16(acc[m][2 * g + 1], ah[m], bl[g][1], bl[g][3]);
            }
    }
}

// Warp GEMM M32 x (2 x N16), 2-term, shared A: 6 ldsm feed 16 MMAs.
template<int NI, int AS, int BS, int LO>
__device__ __forceinline__ void mma_block_n16_pair_2t(unsigned aB, unsigned b0B, unsigned b1B,
                                                      float (&acc)[2][2][2][4]) {
    int lane = threadIdx.x & 31;
    unsigned ar = aB + (lane & 15) * AS + (lane >> 4) * 16;
    unsigned br0 = b0B + (lane & 15) * BS + (lane >> 4) * 16;
    unsigned br1 = b1B + (lane & 15) * BS + (lane >> 4) * 16;
    #pragma unroll 1
    for (int i = 0; i < NI; ++i) {
        unsigned ah[2][4], bh[2][4], bl[2][4];
        ldsm4(ar + 32 * i,           ah[0][0], ah[0][1], ah[0][2], ah[0][3]);
        ldsm4(ar + 16 * AS + 32 * i, ah[1][0], ah[1][1], ah[1][2], ah[1][3]);
        ldsm4(br0 + 32 * i,      bh[0][0], bh[0][1], bh[0][2], bh[0][3]);
        ldsm4(br0 + LO + 32 * i, bl[0][0], bl[0][1], bl[0][2], bl[0][3]);
        ldsm4(br1 + 32 * i,      bh[1][0], bh[1][1], bh[1][2], bh[1][3]);
        ldsm4(br1 + LO + 32 * i, bl[1][0], bl[1][1], bl[1][2], bl[1][3]);
        #pragma unroll
        for (int b = 0; b < 2; ++b)
            #pragma unroll
            for (int m = 0; m < 2; ++m) {
                mma_f16(acc[b][m][0], ah[m], bh[b][0], bh[b][2]);
                mma_f16(acc[b][m][1], ah[m], bh[b][1], bh[b][3]);
                mma_f16(acc[b][m][0], ah[m], bl[b][0], bl[b][2]);
                mma_f16(acc[b][m][1], ah[m], bl[b][1], bl[b][3]);
            }
    }
}

// ---------------------------------------------------------------------------
// Prep: split W2/W3 into fp16 hi/lo padded rows.
// ---------------------------------------------------------------------------
__global__ void prep_w2(const float* __restrict__ cw2) {
    int idx = blockIdx.x * 256 + threadIdx.x;   // 128 x 64
    if (idx >= 128 * 64) return;
    int j = idx >> 6, k = idx & 63;
    float w = cw2[idx];
    __half hi = __float2half(w);
    __half lo = __float2half(w - __half2float(hi));
    g_w2p[j * 136 + k] = hi;
    g_w2p[j * 136 + 64 + k] = lo;
}
__global__ void prep_w3(const float* __restrict__ cw3) {
    int idx = blockIdx.x * 256 + threadIdx.x;   // 256 x 128
    if (idx >= 256 * 128) return;
    int j = idx >> 7, k = idx & 127;
    float w = cw3[idx];
    __half hi = __float2half(w);
    __half lo = __float2half(w - __half2float(hi));
    g_w3p[j * 264 + k] = hi;
    g_w3p[j * 264 + 128 + k] = lo;
}

// ---------------------------------------------------------------------------
// Kernel A: cylinder grouping (unchanged from round 14, passing).
// ---------------------------------------------------------------------------
#define GCHUNK 2048
#define GBUF (GCHUNK * 3)
__global__ __launch_bounds__(256) void group_kernel(
    const float* __restrict__ seed, const float* __restrict__ pc,
    const float* __restrict__ rot)
{
    extern __shared__ float gs[];
    int t = threadIdx.x, wid = t >> 5, lane = t & 31;
    int gw = blockIdx.x * 8 + wid;
    int b = gw >> 10;

    const float* sd = seed + (size_t)gw * 3;
    float sx = sd[0], sy = sd[1], sz = sd[2];
    const float* R = rot + (size_t)gw * 9;
    float r00 = R[0], r01 = R[1], r02 = R[2];
    float r10 = R[3], r11 = R[4], r12 = R[5];
    float r20 = R[6], r21 = R[7], r22 = R[8];
    const float* P = pc + (size_t)b * NPTS * 3;

    #pragma unroll
    for (int q = 0; q < 6; ++q)
        cpasync16(gs + (q * 256 + t) * 4, P + (q * 256 + t) * 4);
    cpcommit();

    int cnt[4] = {0, 0, 0, 0};
    float fx[4], fy[4], fz[4];
    float p0x = 0.f, p0y = 0.f, p0z = 0.f;
    const float hmax[4] = {0.1f, 0.2f, 0.3f, 0.4f};
    float* fb = g_feat + (size_t)gw * NDEPTH * NSAMP * 3;
    unsigned below = (1u << lane) - 1u;

    for (int c = 0; c < NPTS / GCHUNK; ++c) {
        asm volatile("cp.async.wait_group 0;");
        __syncthreads();
        if (c + 1 < NPTS / GCHUNK) {
            const float* src = P + (size_t)(c + 1) * GBUF;
            float* dst = gs + ((c + 1) & 1) * GBUF;
            #pragma unroll
            for (int q = 0; q < 6; ++q)
                cpasync16(dst + (q * 256 + t) * 4, src + (q * 256 + t) * 4);
            cpcommit();
        }
        const float* S = gs + (c & 1) * GBUF;
        float cx = S[lane * 3 + 0], cy = S[lane * 3 + 1], cz = S[lane * 3 + 2];
        for (int ii = 0; ii < GCHUNK / 32; ++ii) {
            float nx = 0.f, ny = 0.f, nz = 0.f;
            if (ii + 1 < GCHUNK / 32) {
                int ni = (ii + 1) * 32 + lane;
                nx = S[ni * 3 + 0]; ny = S[ni * 3 + 1]; nz = S[ni * 3 + 2];
            }
            float rx = cx - sx, ry = cy - sy, rz = cz - sz;
            float ax = rx * r00 + ry * r10 + rz * r20;
            float ay = rx * r01 + ry * r11 + rz * r21;
            float az = rx * r02 + ry * r12 + rz * r22;
            float rr = ay * ay + az * az;
            if (c == 0 && ii == 0) {
                p0x = __shfl_sync(0xffffffffu, ax, 0);
                p0y = __shfl_sync(0xffffffffu, ay, 0);
                p0z = __shfl_sync(0xffffffffu, az, 0);
            }
            bool m3 = (ax > -0.2f) && (ax < 0.4f) && (rr < 0.09f);
            unsigned bal3 = __ballot_sync(0xffffffffu, m3);
            if (bal3) {
                #pragma unroll
                for (int d = 0; d < 4; ++d) {
                    bool m = m3 && (ax < hmax[d]);
                    unsigned bal = (d == 3) ? bal3 : __ballot_sync(0xffffffffu, m);
                    if (bal) {
                        if (cnt[d] == 0) {
                            int src = __ffs(bal) - 1;
                            fx[d] = __shfl_sync(0xffffffffu, ax, src);
                            fy[d] = __shfl_sync(0xffffffffu, ay, src);
                            fz[d] = __shfl_sync(0xffffffffu, az, src);
                        }
                        int pos = cnt[d] + __popc(bal & below);
                        if (m && pos < NSAMP) {
                            float* o = fb + ((size_t)d * NSAMP + pos) * 3;
                            o[0] = ax; o[1] = ay; o[2] = az;
                        }
                        cnt[d] += __popc(bal);
                    }
                }
            }
            cx = nx; cy = ny; cz = nz;
        }
    }
    #pragma unroll
    for (int d = 0; d < 4; ++d) {
        if (cnt[d] < NSAMP) {
            float vx, vy, vz;
            if (cnt[d] > 0) { vx = fx[d]; vy = fy[d]; vz = fz[d]; }
            else           { vx = p0x;   vy = p0y;   vz = p0z;   }
            for (int pos = cnt[d] + lane; pos < NSAMP; pos += 32) {
                float* o = fb + ((size_t)d * NSAMP + pos) * 3;
                o[0] = vx; o[1] = vy; o[2] = vz;
            }
        }
    }
}

// ---------------------------------------------------------------------------
// Kernel B: fp16 2-term scheme. A tiles single fp16, W tiles fp16 hi+lo.
// MMA count -33% vs 3-term bf16; smem 95.2KB, 2 CTAs/SM.
// ---------------------------------------------------------------------------
#define FSC1 0
#define FSH1 64
#define FSC2 128
#define FSH2 256
#define FSC3 384
#define FSH3 640
#define FW1  896
#define FFEAT 1088     // 384 floats
#define FRBMAX 1472    // 4 x 64
#define FRBMIN 1728    // 4 x 64
// byte offsets
#define SB_A2 8192u    // 128 x 144B = 18432
#define SB_B2 26624u   // 128 x 272B = 34816 -> end 61440
#define SB_A3 8192u    // 128 x 272B = 34816 (over A2+B2, written after sync)
#define SB_B3Q0 61440u // 32 x 528B = 16896
#define SB_B3Q1 78336u
#define SMEM_B_BYTES 95232

__global__ __launch_bounds__(256, 2) void mlp_kernel(
    const float* __restrict__ cw1, const float* __restrict__ cbn1,
    const float* __restrict__ cbn2, const float* __restrict__ cbn3)
{
    extern __shared__ float sm[];
    char* smc = (char*)sm;
    int t = threadIdx.x, wid = t >> 5, lane = t & 31;
    int g0 = blockIdx.x * 2;
    unsigned sb = (unsigned)__cvta_generic_to_shared(sm);
    int mw = wid >> 1, nw = wid & 1;   // mw 0..3 (M), nw 0..1 (N)

    // stage: B2 (fp16 split), then W3 pair0 (Q0+Q1 contiguous)
    #pragma unroll
    for (int q = 0; q < 9; ++q) {
        int e = q * 256 + t;
        if (e < 2176) cpasync16(smc + SB_B2 + e * 16, (const char*)g_w2p + e * 16);
    }
    cpcommit();
    #pragma unroll
    for (int q = 0; q < 9; ++q) {
        int e = q * 256 + t;
        if (e < 2112) cpasync16(smc + SB_B3Q0 + e * 16, (const char*)g_w3p + e * 16);
    }
    cpcommit();

    // consts + w1 + feat (2 groups)
    if (t < 64) {
        float sc = cbn1[t] * rsqrtf(cbn1[192 + t] + 1e-5f);
        sm[FSC1 + t] = sc; sm[FSH1 + t] = cbn1[64 + t] - cbn1[128 + t] * sc;
    }
    if (t < 128) {
        float sc = cbn2[t] * rsqrtf(cbn2[384 + t] + 1e-5f);
        sm[FSC2 + t] = sc; sm[FSH2 + t] = cbn2[128 + t] - cbn2[256 + t] * sc;
    }
    {
        float sc = cbn3[t] * rsqrtf(cbn3[768 + t] + 1e-5f);
        sm[FSC3 + t] = sc; sm[FSH3 + t] = cbn3[256 + t] - cbn3[512 + t] * sc;
    }
    if (t < 192) sm[FW1 + t] = cw1[t];
    for (int idx = t; idx < 384; idx += 256)
        sm[FFEAT + idx] = g_feat[(size_t)g0 * 192 + idx];
    __syncthreads();

    // --- Layer 1: 128 samples x 64 ch, single fp16 into A2 ---
    #pragma unroll
    for (int q = 0; q < 32; ++q) {
        int o = q * 256 + t;
        int s = o >> 6, j = o & 63;
        const float* f = sm + FFEAT + s * 3;
        float x = f[0] * sm[FW1 + j * 3 + 0]
                + f[1] * sm[FW1 + j * 3 + 1]
                + f[2] * sm[FW1 + j * 3 + 2];
        x = fmaxf(x * sm[FSC1 + j] + sm[FSH1 + j], 0.f);
        *(__half*)(smc + SB_A2 + s * 144 + 2 * j) = __float2half(x);
    }
    asm volatile("cp.async.wait_group 1;");   // B2 resident
    __syncthreads();

    // --- Layer 2: M128 x N128 x K64, 2-term fp16 HMMA ---
    {
        float acc[2][8][4];
        #pragma unroll
        for (int m = 0; m < 2; ++m)
            #pragma unroll
            for (int g = 0; g < 8; ++g)
                #pragma unroll
                for (int c = 0; c < 4; ++c) acc[m][g][c] = 0.f;
        mma_block_n64_2t<4, 144, 272, 128>(sb + SB_A2 + mw * 32 * 144,
                                           sb + SB_B2 + nw * 64 * 272, acc);
        __syncthreads();   // all reads of A2/B2 done before A3 overwrite

        int r0b = mw * 32 + (lane >> 2);
        int j0b = nw * 64 + 2 * (lane & 3);
        #pragma unroll
        for (int m = 0; m < 2; ++m)
            #pragma unroll
            for (int g = 0; g < 8; ++g) {
                int j0 = j0b + g * 8;
                float sc0 = sm[FSC2 + j0], sh0 = sm[FSH2 + j0];
                float sc1 = sm[FSC2 + j0 + 1], sh1 = sm[FSH2 + j0 + 1];
                #pragma unroll
                for (int rh = 0; rh < 2; ++rh) {
                    int s = r0b + m * 16 + rh * 8;
                    float x0 = fmaxf(acc[m][g][2 * rh + 0] * sc0 + sh0, 0.f);
                    float x1 = fmaxf(acc[m][g][2 * rh + 1] * sc1 + sh1, 0.f);
                    __half2 h;
                    h.x = __float2half(x0);
                    h.y = __float2half(x1);
                    *(__half2*)(smc + SB_A3 + s * 272 + 2 * j0) = h;
                }
            }
    }
    __syncthreads();

    // --- Layer 3: 4 quarter-PAIRS (2 x N16 buffers, shared A), 2-term ---
    #pragma unroll 1
    for (int p = 0; p < 4; ++p) {
        asm volatile("cp.async.wait_group 0;");
        __syncthreads();

        float acc[2][2][2][4];
        #pragma unroll
        for (int b = 0; b < 2; ++b)
            #pragma unroll
            for (int m = 0; m < 2; ++m)
                #pragma unroll
                for (int g = 0; g < 2; ++g)
                    #pragma unroll
                    for (int c = 0; c < 4; ++c) acc[b][m][g][c] = 0.f;
        mma_block_n16_pair_2t<8, 272, 528, 256>(
            sb + SB_A3 + mw * 32 * 272,
            sb + SB_B3Q0 + nw * 16 * 528,
            sb + SB_B3Q1 + nw * 16 * 528, acc);

        #pragma unroll
        for (int b = 0; b < 2; ++b)
            #pragma unroll
            for (int g = 0; g < 2; ++g) {
                float mx0 = -1e30f, mn0 = 1e30f, mx1 = -1e30f, mn1 = 1e30f;
                #pragma unroll
                for (int m = 0; m < 2; ++m)
                    #pragma unroll
                    for (int rh = 0; rh < 2; ++rh) {
                        float v0 = acc[b][m][g][2 * rh + 0], v1 = acc[b][m][g][2 * rh + 1];
                        mx0 = fmaxf(mx0, v0); mn0 = fminf(mn0, v0);
                        mx1 = fmaxf(mx1, v1); mn1 = fminf(mn1, v1);
                    }
                #pragma unroll
                for (int off = 4; off <= 16; off <<= 1) {
                    mx0 = fmaxf(mx0, __shfl_xor_sync(0xffffffffu, mx0, off));
                    mn0 = fminf(mn0, __shfl_xor_sync(0xffffffffu, mn0, off));
                    mx1 = fmaxf(mx1, __shfl_xor_sync(0xffffffffu, mx1, off));
                    mn1 = fminf(mn1, __shfl_xor_sync(0xffffffffu, mn1, off));
                }
                if ((lane >> 2) == 0) {
                    int chl = b * 32 + nw * 16 + g * 8 + 2 * (lane & 3);
                    sm[FRBMAX + mw * 64 + chl] = mx0;
                    sm[FRBMAX + mw * 64 + chl + 1] = mx1;
                    sm[FRBMIN + mw * 64 + chl] = mn0;
                    sm[FRBMIN + mw * 64 + chl + 1] = mn1;
                }
            }
        __syncthreads();

        if (t < 128) {
            int g = t >> 6, c64 = t & 63;
            float mx = fmaxf(sm[FRBMAX + 2 * g * 64 + c64], sm[FRBMAX + (2 * g + 1) * 64 + c64]);
            float mn = fminf(sm[FRBMIN + 2 * g * 64 + c64], sm[FRBMIN + (2 * g + 1) * 64 + c64]);
            int j = p * 64 + c64;
            float sc = sm[FSC3 + j], sh = sm[FSH3 + j];
            float val = (sc >= 0.f) ? sc * mx + sh : sc * mn + sh;
            g_vp[(size_t)(g0 + g) * 256 + j] = fmaxf(val, 0.f);
        }
        if (p < 3) {
            char* dst = smc + SB_B3Q0;
            const char* src = (const char*)g_w3p + (2 * p + 2) * 16896;
            #pragma unroll
            for (int qq = 0; qq < 9; ++qq) {
                int e = qq * 256 + t;
                if (e < 2112) cpasync16(dst + e * 16, src + e * 16);
            }
            cpcommit();
        }
    }
}

// ---------------------------------------------------------------------------
// Kernel C: both heads, 16 rows per block (unchanged from round 14, passing).
// ---------------------------------------------------------------------------
#define HR 16
#define SMEM_C_FLOATS (HR*256*3 + 256*4 + 256*34 + 48*130)
#define SMEM_C_BYTES  (SMEM_C_FLOATS * 4)   // 113024

__global__ __launch_bounds__(256) void head_kernel(
    const float* __restrict__ ow1, const float* __restrict__ ob1, const float* __restrict__ obn1,
    const float* __restrict__ ow2, const float* __restrict__ ob2, const float* __restrict__ obn2,
    const float* __restrict__ ow3, const float* __restrict__ ob3,
    const float* __restrict__ tw1, const float* __restrict__ tb1, const float* __restrict__ tbn1,
    const float* __restrict__ tw2, const float* __restrict__ tb2, const float* __restrict__ tbn2,
    const float* __restrict__ tw3, const float* __restrict__ tb3,
    float* __restrict__ out)
{
    extern __shared__ float sm[];
    float* s_vp = sm;                  // HR x 256
    float* s_h1 = s_vp + HR * 256;
    float* s_h2 = s_h1 + HR * 256;
    float* sA1  = s_h2 + HR * 256;
    float* hA1  = sA1 + 256;
    float* sA2  = hA1 + 256;
    float* hA2  = sA2 + 256;
    float* s_wt = hA2 + 256;           // 256 x 34
    float* s_w3 = s_wt + 256 * 34;     // 48 x 130

    int t = threadIdx.x;
    int row0 = blockIdx.x * HR;

    {
        int c = t & 127;
        if (t < 128) {
            float sc = obn1[c] * rsqrtf(obn1[384 + c] + 1e-5f);
            sA1[t] = sc; hA1[t] = (ob1[c] - obn1[256 + c]) * sc + obn1[128 + c];
            float s2 = obn2[c] * rsqrtf(obn2[384 + c] + 1e-5f);
            sA2[t] = s2; hA2[t] = (ob2[c] - obn2[256 + c]) * s2 + obn2[128 + c];
        } else {
            float sc = tbn1[c] * rsqrtf(tbn1[384 + c] + 1e-5f);
            sA1[t] = sc; hA1[t] = (tb1[c] - tbn1[256 + c]) * sc + tbn1[128 + c];
            float s2 = tbn2[c] * rsqrtf(tbn2[384 + c] + 1e-5f);
            sA2[t] = s2; hA2[t] = (tb2[c] - tbn2[256 + c]) * s2 + tbn2[128 + c];
        }
    }
    for (int idx = t; idx < HR * 256; idx += 256)
        s_vp[idx] = g_vp[(size_t)row0 * 256 + idx];
    for (int idx = t; idx < 48 * 128; idx += 256) {
        int r = idx >> 7, c = idx & 127;
        s_w3[r * 130 + c] = (r < 36) ? ow3[r * 128 + c] : tw3[(r - 36) * 128 + c];
    }
    __syncthreads();

    ull acc2[HR];
    // Layer 1
    #pragma unroll
    for (int r = 0; r < HR; ++r) acc2[r] = 0ull;
    for (int i0 = 0; i0 < 256; i0 += 32) {
        #pragma unroll
        for (int q = 0; q < 32; ++q) {
            int idx = q * 256 + t; int r = idx >> 5, c = idx & 31;
            s_wt[r * 34 + c] = (r < 128) ? ow1[r * 256 + i0 + c]
                                         : tw1[(r - 128) * 256 + i0 + c];
        }
        __syncthreads();
        #pragma unroll
        for (int p = 0; p < 16; ++p) {
            ull w = *(const ull*)(s_wt + t * 34 + 2 * p);
            #pragma unroll
            for (int r = 0; r < HR; ++r) {
                ull a = *(const ull*)(s_vp + r * 256 + i0 + 2 * p);
                fma2(acc2[r], a, w);
            }
        }
        __syncthreads();
    }
    #pragma unroll
    for (int r = 0; r < HR; ++r)
        s_h1[r * 256 + t] = fmaxf(hsum2(acc2[r]) * sA1[t] + hA1[t], 0.f);
    __syncthreads();

    // Layer 2
    #pragma unroll
    for (int r = 0; r < HR; ++r) acc2[r] = 0ull;
    int hbase = t & 128;
    for (int i0 = 0; i0 < 128; i0 += 32) {
        #pragma unroll
        for (int q = 0; q < 32; ++q) {
            int idx = q * 256 + t; int r = idx >> 5, c = idx & 31;
            s_wt[r * 34 + c] = (r < 128) ? ow2[r * 128 + i0 + c]
                                         : tw2[(r - 128) * 128 + i0 + c];
        }
        __syncthreads();
        #pragma unroll
        for (int p = 0; p < 16; ++p) {
            ull w = *(const ull*)(s_wt + t * 34 + 2 * p);
            #pragma unroll
            for (int r = 0; r < HR; ++r) {
                ull a = *(const ull*)(s_h1 + r * 256 + hbase + i0 + 2 * p);
                fma2(acc2[r], a, w);
            }
        }
        __syncthreads();
    }
    #pragma unroll
    for (int r = 0; r < HR; ++r)
        s_h2[r * 256 + t] = fmaxf(hsum2(acc2[r]) * sA2[t] + hA2[t], 0.f);
    __syncthreads();

    // Layer 3: 16 threads/row, 3 channels each, transposed out
    {
        int r = t >> 4, c0 = t & 15;
        #pragma unroll
        for (int third = 0; third < 3; ++third) {
            int cc = c0 + third * 16;   // 0..47
            int hb = (cc < 36) ? 0 : 128;
            const float* wrow = s_w3 + cc * 130;
            ull a2 = 0ull;
            #pragma unroll 8
            for (int p = 0; p < 64; ++p) {
                ull a = *(const ull*)(s_h2 + r * 256 + hb + 2 * p);
                ull w = *(const ull*)(wrow + 2 * p);
                fma2(a2, a, w);
            }
            float a = hsum2(a2) + ((cc < 36) ? ob3[cc] : tb3[cc - 36]);
            int row = row0 + r;
            int b = row >> 12, rr = row & 4095, s = rr >> 2, d = rr & 3;
            out[(((size_t)b * 48 + cc) * 1024 + s) * 4 + d] = a;
        }
    }
}

// ---------------------------------------------------------------------------
extern "C" void kernel_launch(void* const* d_in, const int* in_sizes, int n_in,
                              void* d_out, int out_size)
{
    (void)in_sizes; (void)n_in; (void)out_size;
    const float* seed = (const float*)d_in[0];
    const float* pc   = (const float*)d_in[1];
    const float* rot  = (const float*)d_in[2];
    const float* cw1  = (const float*)d_in[3];
    const float* cbn1 = (const float*)d_in[4];
    const float* cw2  = (const float*)d_in[5];
    const float* cbn2 = (const float*)d_in[6];
    const float* cw3  = (const float*)d_in[7];
    const float* cbn3 = (const float*)d_in[8];
    const float* ow1  = (const float*)d_in[9];
    const float* ob1  = (const float*)d_in[10];
    const float* obn1 = (const float*)d_in[11];
    const float* ow2  = (const float*)d_in[12];
    const float* ob2  = (const float*)d_in[13];
    const float* obn2 = (const float*)d_in[14];
    const float* ow3  = (const float*)d_in[15];
    const float* ob3  = (const float*)d_in[16];
    const float* tw1  = (const float*)d_in[17];
    const float* tb1  = (const float*)d_in[18];
    const float* tbn1 = (const float*)d_in[19];
    const float* tw2  = (const float*)d_in[20];
    const float* tb2  = (const float*)d_in[21];
    const float* tbn2 = (const float*)d_in[22];
    const float* tw3  = (const float*)d_in[23];
    const float* tb3  = (const float*)d_in[24];
    float* out = (float*)d_out;

    cudaFuncSetAttribute(group_kernel, cudaFuncAttributeMaxDynamicSharedMemorySize, 49152);
    cudaFuncSetAttribute(mlp_kernel,  cudaFuncAttributeMaxDynamicSharedMemorySize, SMEM_B_BYTES);
    cudaFuncSetAttribute(head_kernel, cudaFuncAttributeMaxDynamicSharedMemorySize, SMEM_C_BYTES);

    prep_w2<<<32, 256>>>(cw2);
    prep_w3<<<128, 256>>>(cw3);
    group_kernel<<<256, 256, 49152>>>(seed, pc, rot);
    mlp_kernel<<<NSEED * NDEPTH, 256, SMEM_B_BYTES>>>(cw1, cbn1, cbn2, cbn3);
    head_kernel<<<2 * NSEED * NDEPTH / HR, 256, SMEM_C_BYTES>>>(
        ow1, ob1, obn1, ow2, ob2, obn2, ow3, ob3,
        tw1, tb1, tbn1, tw2, tb2, tbn2, tw3, tb3, out);
}